// round 15
// baseline (speedup 1.0000x reference)
#include <cuda_runtime.h>
#include <cstdint>

// Per-token int4 quantization — hybrid: 256-bit loads + R8's float2 stores.
//   x: [N, H] fp32 (H = 4096)
//   scales[n] = max|x[n,:]| / 7
//   q = rint(x * 7/max)   (in [-7,7] by construction; clamp-free)
//   packed byte = ((q_odd & 0xF) << 4) | (q_even & 0xF)  (signed int8 value)
//
// Loads : 2x ld.global.cs.v8.f32 per thread (1KB/warp/instr, lane-consecutive)
//         — measured +8% HBM throughput vs LDG.128 (R14).
// Stores: float2 default write-back, R8 shape — measured minimal DRAM write
//         traffic via graph-replay overwrite residency (R8: ~145MB total).
//
// Harness output layout (detected via out_size):
//   FLOAT_OUT: [N*H/2 float32 (packed byte values)][N float32 scales]
//   BYTE_OUT : [N*H/2 int8][N float32 scales]

constexpr int H       = 4096;
constexpr int THREADS = 256;
constexpr int VLOADS  = H / 8 / THREADS;  // 2 v8-loads per thread

struct f8 { float v[8]; };

__device__ __forceinline__ f8 ldg256_cs(const float* p)
{
    f8 r;
    asm volatile("ld.global.cs.v8.f32 {%0,%1,%2,%3,%4,%5,%6,%7}, [%8];"
                 : "=f"(r.v[0]), "=f"(r.v[1]), "=f"(r.v[2]), "=f"(r.v[3]),
                   "=f"(r.v[4]), "=f"(r.v[5]), "=f"(r.v[6]), "=f"(r.v[7])
                 : "l"(p));
    return r;
}

template <bool FLOAT_OUT>
__global__ __launch_bounds__(THREADS, 8)
void quant_int4_kernel(const float* __restrict__ x,
                       void* __restrict__ packed_out,
                       float* __restrict__ scales)
{
    const int row = blockIdx.x;
    const int t   = threadIdx.x;

    const float* xr = x + (size_t)row * H;

    // 2 front-batched 256-bit streaming loads, lane-consecutive.
    f8 v[VLOADS];
#pragma unroll
    for (int k = 0; k < VLOADS; ++k)
        v[k] = ldg256_cs(xr + 8 * (t + THREADS * k));

    // Local max|x|
    float m = 0.0f;
#pragma unroll
    for (int k = 0; k < VLOADS; ++k)
#pragma unroll
        for (int i = 0; i < 8; ++i)
            m = fmaxf(m, fabsf(v[k].v[i]));

    // Warp reduce
#pragma unroll
    for (int o = 16; o > 0; o >>= 1)
        m = fmaxf(m, __shfl_xor_sync(0xffffffffu, m, o));

    __shared__ float smax[THREADS / 32];
    if ((t & 31) == 0) smax[t >> 5] = m;
    __syncthreads();

    float rowmax = smax[0];
#pragma unroll
    for (int w = 1; w < THREADS / 32; ++w)
        rowmax = fmaxf(rowmax, smax[w]);

    const float scale = rowmax / 7.0f;                        // exact fp32
    const float inv   = (rowmax > 0.0f) ? 7.0f / rowmax : 0.0f;

    if (t == 0) scales[row] = scale;

    // Quantize: 8 floats -> 4 packed byte values per v8 load. Clamp-free.
    // Store shape identical to R8: float2 per instruction, default write-back,
    // addresses {2t, 2t+... } — lane-consecutive 8B units.
    if (FLOAT_OUT) {
        float2* op = reinterpret_cast<float2*>((float*)packed_out + (size_t)row * (H / 2));
#pragma unroll
        for (int k = 0; k < VLOADS; ++k) {
            float b[4];
#pragma unroll
            for (int i = 0; i < 4; ++i) {
                // rintf == FRND round-half-even, matches reference rounding.
                float q0 = rintf(v[k].v[2 * i + 0] * inv);
                float q1 = rintf(v[k].v[2 * i + 1] * inv);
                // low-nibble value: q + 16 if q < 0 (maps [-8,-1] -> [8,15])
                float n0 = q0 + (q0 < 0.0f ? 16.0f : 0.0f);
                b[i] = fmaf(16.0f, q1, n0);   // exact: small integers
            }
            op[2 * (t + THREADS * k) + 0] = make_float2(b[0], b[1]);
            op[2 * (t + THREADS * k) + 1] = make_float2(b[2], b[3]);
        }
    } else {
        uint16_t* op = reinterpret_cast<uint16_t*>((int8_t*)packed_out + (size_t)row * (H / 2));
#pragma unroll
        for (int k = 0; k < VLOADS; ++k) {
#pragma unroll
            for (int i = 0; i < 2; ++i) {
                int q0 = __float2int_rn(v[k].v[4 * i + 0] * inv);
                int q1 = __float2int_rn(v[k].v[4 * i + 1] * inv);
                int q2 = __float2int_rn(v[k].v[4 * i + 2] * inv);
                int q3 = __float2int_rn(v[k].v[4 * i + 3] * inv);
                op[2 * (t + THREADS * k) + i] =
                    (uint16_t)((((q3 & 0xF) << 4) | (q2 & 0xF)) << 8
                             | (((q1 & 0xF) << 4) | (q0 & 0xF)));
            }
        }
    }
}

extern "C" void kernel_launch(void* const* d_in, const int* in_sizes, int n_in,
                              void* d_out, int out_size)
{
    const float* x = (const float*)d_in[0];
    const int rows = in_sizes[0] / H;
    const long long packed_elems = (long long)rows * (H / 2);

    if ((long long)out_size == packed_elems + rows) {
        // float32 layout: packed values as floats, then scales
        float* packed = (float*)d_out;
        float* scales = packed + packed_elems;
        quant_int4_kernel<true><<<rows, THREADS>>>(x, packed, scales);
    } else {
        // int8 layout: packed bytes, then fp32 scales appended as raw bytes
        int8_t* packed = (int8_t*)d_out;
        float*  scales = (float*)(packed + packed_elems);
        quant_int4_kernel<false><<<rows, THREADS>>>(x, packed, scales);
    }
}

// round 16
// speedup vs baseline: 1.0800x; 1.0800x over previous
#include <cuda_runtime.h>
#include <cstdint>

// Per-token int4 quantization (single-pass, block-per-row) — FINAL (R8 config):
//   x: [N, H] fp32 (H = 4096)
//   scales[n] = max|x[n,:]| / 7
//   q = rint(x * 7/max)   (in [-7,7] by construction; clamp-free)
//   packed byte = ((q_odd & 0xF) << 4) | (q_even & 0xF)  (signed int8 value)
//
// Measured optimum over 15 rounds:
//   - float4 loads, __ldcs (streaming; input read exactly once)
//   - lane-consecutive float2 write-back stores (replay-overwrite keeps most
//     of the 64MB write set L2-resident: ~145MB DRAM traffic vs 134MB reads)
//   - 256 thr/CTA, 4 front-batched LDG.128/thread (register sweet spot)
//   - one CTA per row, classic launch (perfect-balance wave schedule)
// Rejected by measurement: persistent CTAs, 2-row fused/sequenced, warp-per-
// row two-pass, 128-thr CTAs, v8.256 loads (store-shape coupling), evict_last.
//
// Harness output layout (detected via out_size):
//   FLOAT_OUT: [N*H/2 float32 (packed byte values)][N float32 scales]
//   BYTE_OUT : [N*H/2 int8][N float32 scales]

constexpr int H       = 4096;
constexpr int THREADS = 256;
constexpr int CHUNKS  = H / 4 / THREADS;  // 4 float4-chunks per thread

template <bool FLOAT_OUT>
__global__ __launch_bounds__(THREADS, 8)
void quant_int4_kernel(const float* __restrict__ x,
                       void* __restrict__ packed_out,
                       float* __restrict__ scales)
{
    const int row = blockIdx.x;
    const int t   = threadIdx.x;

    const float4* xr = reinterpret_cast<const float4*>(x + (size_t)row * H);

    // Coalesced streaming loads: lane-consecutive float4 per LDG.128,
    // all 4 front-batched for max MLP.
    float4 v[CHUNKS];
#pragma unroll
    for (int k = 0; k < CHUNKS; ++k)
        v[k] = __ldcs(&xr[t + THREADS * k]);

    // Local max|x|
    float m = 0.0f;
#pragma unroll
    for (int k = 0; k < CHUNKS; ++k) {
        m = fmaxf(m, fmaxf(fmaxf(fabsf(v[k].x), fabsf(v[k].y)),
                           fmaxf(fabsf(v[k].z), fabsf(v[k].w))));
    }

    // Warp reduce
#pragma unroll
    for (int o = 16; o > 0; o >>= 1)
        m = fmaxf(m, __shfl_xor_sync(0xffffffffu, m, o));

    __shared__ float smax[THREADS / 32];
    if ((t & 31) == 0) smax[t >> 5] = m;
    __syncthreads();

    float rowmax = smax[0];
#pragma unroll
    for (int w = 1; w < THREADS / 32; ++w)
        rowmax = fmaxf(rowmax, smax[w]);

    const float scale = rowmax / 7.0f;                        // exact fp32
    const float inv   = (rowmax > 0.0f) ? 7.0f / rowmax : 0.0f;

    if (t == 0) scales[row] = scale;

    // Quantize each float4 chunk -> 2 packed byte values. Clamp-free:
    // |x| <= rowmax implies |x*inv| <= 7 (+1ulp), rint stays in [-7,7].
    if (FLOAT_OUT) {
        float2* op = reinterpret_cast<float2*>((float*)packed_out + (size_t)row * (H / 2));
#pragma unroll
        for (int k = 0; k < CHUNKS; ++k) {
            // rintf == FRND round-half-even, matches reference rounding.
            float q0 = rintf(v[k].x * inv);
            float q1 = rintf(v[k].y * inv);
            float q2 = rintf(v[k].z * inv);
            float q3 = rintf(v[k].w * inv);
            // low-nibble value: q + 16 if q < 0 (maps [-8,-1] -> [8,15])
            float n0 = q0 + (q0 < 0.0f ? 16.0f : 0.0f);
            float n2 = q2 + (q2 < 0.0f ? 16.0f : 0.0f);
            float b0 = fmaf(16.0f, q1, n0);   // exact: small integers
            float b1 = fmaf(16.0f, q3, n2);
            op[t + THREADS * k] = make_float2(b0, b1);   // default write-back
        }
    } else {
        uint16_t* op = reinterpret_cast<uint16_t*>((int8_t*)packed_out + (size_t)row * (H / 2));
#pragma unroll
        for (int k = 0; k < CHUNKS; ++k) {
            int q0 = __float2int_rn(v[k].x * inv);
            int q1 = __float2int_rn(v[k].y * inv);
            int q2 = __float2int_rn(v[k].z * inv);
            int q3 = __float2int_rn(v[k].w * inv);
            uint16_t b = (uint16_t)((((q3 & 0xF) << 4) | (q2 & 0xF)) << 8
                                  | (((q1 & 0xF) << 4) | (q0 & 0xF)));
            op[t + THREADS * k] = b;
        }
    }
}

extern "C" void kernel_launch(void* const* d_in, const int* in_sizes, int n_in,
                              void* d_out, int out_size)
{
    const float* x = (const float*)d_in[0];
    const int rows = in_sizes[0] / H;
    const long long packed_elems = (long long)rows * (H / 2);

    if ((long long)out_size == packed_elems + rows) {
        // float32 layout: packed values as floats, then scales
        float* packed = (float*)d_out;
        float* scales = packed + packed_elems;
        quant_int4_kernel<true><<<rows, THREADS>>>(x, packed, scales);
    } else {
        // int8 layout: packed bytes, then fp32 scales appended as raw bytes
        int8_t* packed = (int8_t*)d_out;
        float*  scales = (float*)(packed + packed_elems);
        quant_int4_kernel<false><<<rows, THREADS>>>(x, packed, scales);
    }
}